// round 3
// baseline (speedup 1.0000x reference)
#include <cuda_runtime.h>
#include <cuda_bf16.h>
#include <cstdint>

#define NUM_AUTHOR 16604
#define EMBED_DIM  300
#define BATCH      32768
#define KPAD       928        // 900 padded to 29 chunks of 32
#define NPAD       320        // 300 padded
#define NCHUNK     29
#define SMEM_STAGE 46080      // Ahi 10240 + Alo 10240 + Bhi 12800 + Blo 12800

// ---------------- device scratch (allocation-free rule: __device__ globals) ---
__device__ int g_seg_start[BATCH + 1];
__device__ __align__(16) __nv_bfloat16 g_Ahi[(size_t)BATCH * KPAD];
__device__ __align__(16) __nv_bfloat16 g_Alo[(size_t)BATCH * KPAD];
__device__ __align__(16) __nv_bfloat16 g_Whi[NPAD * KPAD];
__device__ __align__(16) __nv_bfloat16 g_Wlo[NPAD * KPAD];

// ---------------- kernel 1: segment boundaries via binary search -------------
__global__ void k_bounds(const int* __restrict__ seg, int E) {
  int b = blockIdx.x * blockDim.x + threadIdx.x;
  if (b > BATCH) return;
  int lo = 0, hi = E;
  while (lo < hi) {
    int mid = (lo + hi) >> 1;
    if (seg[mid] < b) lo = mid + 1; else hi = mid;
  }
  g_seg_start[b] = lo;
}

// split fp32 -> bf16 hi + bf16 lo (residual)
__device__ __forceinline__ void split_store(size_t idx, float x) {
  __nv_bfloat16 h = __float2bfloat16(x);
  g_Ahi[idx] = h;
  g_Alo[idx] = __float2bfloat16(x - __bfloat162float(h));
}

// ---------------- kernel 2: gather + segment mean pool (1 warp / segment) ----
__global__ __launch_bounds__(256) void k_pool(const int* __restrict__ nodes,
                                              const int* __restrict__ neighbors,
                                              const float* __restrict__ emb) {
  const int lane = threadIdx.x & 31;
  const int b = blockIdx.x * 8 + (threadIdx.x >> 5);
  const int n0 = __ldg(nodes + b);
  const bool selfA = n0 < NUM_AUTHOR;
  const int s = g_seg_start[b];
  const int e = g_seg_start[b + 1];

  float s1[10], s2[10];
#pragma unroll
  for (int j = 0; j < 10; j++) { s1[j] = 0.f; s2[j] = 0.f; }
  float c1 = 0.f, c2 = 0.f;

  for (int i = s; i < e; i++) {
    int nb = __ldg(neighbors + i);
    bool same = (nb < NUM_AUTHOR) == selfA;
    const float* row = emb + (size_t)nb * EMBED_DIM;
    float v[10];
#pragma unroll
    for (int j = 0; j < 10; j++)
      v[j] = (j < 9 || lane < 12) ? __ldg(row + lane + 32 * j) : 0.f;
    if (same) {
      c1 += 1.f;
#pragma unroll
      for (int j = 0; j < 10; j++) s1[j] += v[j];
    } else {
      c2 += 1.f;
#pragma unroll
      for (int j = 0; j < 10; j++) s2[j] += v[j];
    }
  }

  const size_t base = (size_t)b * KPAD;
#pragma unroll
  for (int j = 0; j < 10; j++) {
    int d = lane + 32 * j;
    if (j < 9 || lane < 12) {
      float sf = __ldg(emb + (size_t)n0 * EMBED_DIM + d);
      float t1 = (c1 > 0.f) ? (s1[j] / c1) : 1.0f;
      float t2 = (c2 > 0.f) ? (s2[j] / c2) : 1.0f;
      split_store(base + d, sf);
      split_store(base + 300 + d, t1);
      split_store(base + 600 + d, t2);
    }
  }
  if (lane < 28) {  // zero K-pad columns 900..927
    g_Ahi[base + 900 + lane] = __float2bfloat16(0.f);
    g_Alo[base + 900 + lane] = __float2bfloat16(0.f);
  }
}

// ---------------- kernel 3: split + pad W1 into bf16 hi/lo -------------------
__global__ void k_wsplit(const float* __restrict__ W1) {
  int idx = blockIdx.x * blockDim.x + threadIdx.x;
  if (idx >= NPAD * KPAD) return;
  int n = idx / KPAD;
  int k = idx - n * KPAD;
  float w = (n < 300 && k < 900) ? __ldg(W1 + n * 900 + k) : 0.f;
  __nv_bfloat16 h = __float2bfloat16(w);
  g_Whi[idx] = h;
  g_Wlo[idx] = __float2bfloat16(w - __bfloat162float(h));
}

// ---------------- kernel 4: split-bf16 tensor-core GEMM ----------------------
__device__ __forceinline__ void cp16(void* s, const void* g) {
  unsigned sa = (unsigned)__cvta_generic_to_shared(s);
  asm volatile("cp.async.cg.shared.global [%0], [%1], 16;\n" :: "r"(sa), "l"(g));
}

__device__ __forceinline__ uint32_t lds32(const void* p) {
  uint32_t v;
  unsigned a = (unsigned)__cvta_generic_to_shared(p);
  asm volatile("ld.shared.b32 %0, [%1];\n" : "=r"(v) : "r"(a));
  return v;
}

__device__ __forceinline__ void mma16816(float c[4], const uint32_t a[4],
                                         uint32_t b0, uint32_t b1) {
  asm volatile(
      "mma.sync.aligned.m16n8k16.row.col.f32.bf16.bf16.f32 "
      "{%0,%1,%2,%3},{%4,%5,%6,%7},{%8,%9},{%0,%1,%2,%3};\n"
      : "+f"(c[0]), "+f"(c[1]), "+f"(c[2]), "+f"(c[3])
      : "r"(a[0]), "r"(a[1]), "r"(a[2]), "r"(a[3]), "r"(b0), "r"(b1));
}

// Block tile: 128(M) x 160(N), K-chunk 32, 8 warps as 4(m) x 2(n),
// warp tile 32(m) x 80(n) -> 2 m16-tiles x 10 n8-tiles, 3 MMAs per tile (split).
// smem row stride 80 B (40 bf16) -> conflict-free fragment LDS.
__global__ __launch_bounds__(256, 1) void k_gemm(const float* __restrict__ bias,
                                                 float* __restrict__ out) {
  extern __shared__ __align__(16) unsigned char sm_raw[];
  const int tid = threadIdx.x;
  const int lane = tid & 31;
  const int warp = tid >> 5;
  const int wm = warp >> 1;   // 0..3
  const int wn = warp & 1;    // 0..1
  const int m0 = blockIdx.x * 128;
  const int n0 = blockIdx.y * 160;

  float acc[2][10][4];
#pragma unroll
  for (int i = 0; i < 2; i++)
#pragma unroll
    for (int j = 0; j < 10; j++)
#pragma unroll
      for (int k = 0; k < 4; k++) acc[i][j][k] = 0.f;

  const __nv_bfloat16* gAh = g_Ahi + (size_t)m0 * KPAD;
  const __nv_bfloat16* gAl = g_Alo + (size_t)m0 * KPAD;
  const __nv_bfloat16* gWh = g_Whi + (size_t)n0 * KPAD;
  const __nv_bfloat16* gWl = g_Wlo + (size_t)n0 * KPAD;

  auto load_stage = [&](int c, int st) {
    unsigned char* sb = sm_raw + st * SMEM_STAGE;
    const int koff = c * 32;
    for (int i = tid; i < 512; i += 256) {        // A: 128 rows x 4 x 16B
      int row = i >> 2, kc = i & 3;
      size_t goff = (size_t)row * KPAD + koff + kc * 8;
      cp16(sb + row * 80 + kc * 16, gAh + goff);
      cp16(sb + 10240 + row * 80 + kc * 16, gAl + goff);
    }
    for (int i = tid; i < 640; i += 256) {        // B: 160 rows x 4 x 16B
      int row = i >> 2, kc = i & 3;
      size_t goff = (size_t)row * KPAD + koff + kc * 8;
      cp16(sb + 20480 + row * 80 + kc * 16, gWh + goff);
      cp16(sb + 33280 + row * 80 + kc * 16, gWl + goff);
    }
  };

  auto compute = [&](int st) {
    const unsigned char* sb = sm_raw + st * SMEM_STAGE;
#pragma unroll
    for (int kk = 0; kk < 2; kk++) {
      const int cb = kk * 32 + (lane & 3) * 4;
      uint32_t ah[2][4], al[2][4];
#pragma unroll
      for (int mi = 0; mi < 2; mi++) {
        int r = wm * 32 + mi * 16 + (lane >> 2);
        const unsigned char* pa = sb + r * 80 + cb;
        ah[mi][0] = lds32(pa);
        ah[mi][1] = lds32(pa + 640);
        ah[mi][2] = lds32(pa + 16);
        ah[mi][3] = lds32(pa + 656);
        const unsigned char* pl = pa + 10240;
        al[mi][0] = lds32(pl);
        al[mi][1] = lds32(pl + 640);
        al[mi][2] = lds32(pl + 16);
        al[mi][3] = lds32(pl + 656);
      }
#pragma unroll
      for (int ni = 0; ni < 10; ni++) {
        int nr = wn * 80 + ni * 8 + (lane >> 2);
        const unsigned char* pb = sb + 20480 + nr * 80 + cb;
        uint32_t bh0 = lds32(pb);
        uint32_t bh1 = lds32(pb + 16);
        uint32_t bl0 = lds32(pb + 12800);
        uint32_t bl1 = lds32(pb + 12816);
#pragma unroll
        for (int mi = 0; mi < 2; mi++) {
          mma16816(acc[mi][ni], ah[mi], bh0, bh1);   // hi*hi
          mma16816(acc[mi][ni], al[mi], bh0, bh1);   // lo*hi
          mma16816(acc[mi][ni], ah[mi], bl0, bl1);   // hi*lo
        }
      }
    }
  };

  load_stage(0, 0);
  asm volatile("cp.async.commit_group;\n" ::: "memory");
  for (int c = 0; c < NCHUNK; c++) {
    if (c + 1 < NCHUNK) {
      load_stage(c + 1, (c + 1) & 1);
      asm volatile("cp.async.commit_group;\n" ::: "memory");
      asm volatile("cp.async.wait_group 1;\n" ::: "memory");
    } else {
      asm volatile("cp.async.wait_group 0;\n" ::: "memory");
    }
    __syncthreads();
    compute(c & 1);
    __syncthreads();
  }

  // epilogue: +bias, guard n<300 (pad columns dropped)
#pragma unroll
  for (int mi = 0; mi < 2; mi++) {
    int m = m0 + wm * 32 + mi * 16 + (lane >> 2);
#pragma unroll
    for (int ni = 0; ni < 10; ni++) {
      int n = n0 + wn * 80 + ni * 8 + (lane & 3) * 2;
      if (n < 300) {
        float bv0 = __ldg(bias + n);
        float bv1 = __ldg(bias + n + 1);
        float2 r0 = make_float2(acc[mi][ni][0] + bv0, acc[mi][ni][1] + bv1);
        float2 r1 = make_float2(acc[mi][ni][2] + bv0, acc[mi][ni][3] + bv1);
        *reinterpret_cast<float2*>(out + (size_t)m * 300 + n) = r0;
        *reinterpret_cast<float2*>(out + (size_t)(m + 8) * 300 + n) = r1;
      }
    }
  }
}

// ---------------- launch ------------------------------------------------------
extern "C" void kernel_launch(void* const* d_in, const int* in_sizes, int n_in,
                              void* d_out, int out_size) {
  const int* nodes     = (const int*)d_in[0];
  const int* seg       = (const int*)d_in[1];
  const int* neighbors = (const int*)d_in[2];
  const float* emb     = (const float*)d_in[3];
  const float* W1      = (const float*)d_in[4];
  const float* b1      = (const float*)d_in[5];
  float* out = (float*)d_out;
  const int E = in_sizes[1];

  cudaFuncSetAttribute(k_gemm, cudaFuncAttributeMaxDynamicSharedMemorySize,
                       2 * SMEM_STAGE);

  k_bounds<<<(BATCH + 1 + 255) / 256, 256>>>(seg, E);
  k_pool<<<BATCH / 8, 256>>>(nodes, neighbors, emb);
  k_wsplit<<<(NPAD * KPAD + 255) / 256, 256>>>(W1);
  k_gemm<<<dim3(BATCH / 128, NPAD / 160), 256, 2 * SMEM_STAGE>>>(b1, out);
}